// round 11
// baseline (speedup 1.0000x reference)
#include <cuda_runtime.h>
#include <cstdint>

// out[b,i,j,c] = sum_k exp(-2(li-x0k)^2)*exp(-2(lj-x1k)^2)*Yb[k,c]
// GEMM: C[64 x 640] = A[64 x 1024] * Z[1024 x 640], bf16 mma m16n8k16.
// Z = B (x) Yb is PRE-MATERIALIZED in fragment layout (21MB, L2-resident),
// so the mma kernel is a barrier-free streaming GEMM.
#define NB    16
#define NN    1024
#define STEP  (6.0f / 63.0f)
#define EX2C  (-2.885390081777927f)   // -2*log2(e)

// A frags: u32 idx = b*32768 + kstep*512 + slab*128 + lane*4 + q
__device__ __align__(16) uint32_t g_Aperm[NB * 64 * 4 * 32 * 4];
// Z frags: uint2 idx = (((b*16+jt)*64 + kstep)*5 + nc)*32 + lane
__device__ __align__(16) uint2 g_Zperm[NB * 16 * 64 * 5 * 32];

__device__ __forceinline__ float ex2f(float x) {
    float r; asm("ex2.approx.ftz.f32 %0, %1;" : "=f"(r) : "f"(x)); return r;
}
__device__ __forceinline__ uint32_t pack_bf16(float lo, float hi) {
    uint32_t d;
    asm("cvt.rn.bf16x2.f32 %0, %1, %2;" : "=r"(d) : "f"(hi), "f"(lo));
    return d;
}
#define MMA_BF16(d, a, bb) \
    asm volatile("mma.sync.aligned.m16n8k16.row.col.f32.bf16.bf16.f32 " \
        "{%0,%1,%2,%3}, {%4,%5,%6,%7}, {%8,%9}, {%0,%1,%2,%3};" \
        : "+f"(d[0]), "+f"(d[1]), "+f"(d[2]), "+f"(d[3]) \
        : "r"(a.x), "r"(a.y), "r"(a.z), "r"(a.w), "r"(bb.x), "r"(bb.y))

// ---------- prep: A frags (bx<512) + Z frags (bx>=512) + grid coords ----------
__global__ __launch_bounds__(256)
void rkhs_prep_kernel(const float* __restrict__ X, const float* __restrict__ Y,
                      float* __restrict__ out)
{
    const int bx = blockIdx.x;
    const int t  = threadIdx.x;

    if (bx < 512) {
        // ---- A part: 4 u32 per thread, one shared X load ----
        int tid = bx * 256 + t;
        if (tid < 4096) {
            out[tid * 2 + 0] = -3.0f + (float)(tid >> 6) * STEP;
            out[tid * 2 + 1] = -3.0f + (float)(tid & 63) * STEP;
        }
        int q     = tid & 3;
        int lane  = (tid >> 2) & 31;
        int kstep = (tid >> 7) & 63;
        int b     = tid >> 13;

        int kb = kstep * 16 + ((lane & 3) << 1) + ((q >> 1) << 3);
        float4 xx = *(const float4*)(X + (size_t)(b * NN + kb) * 2);
        int rbase = (lane >> 2) + ((q & 1) << 3);
        uint32_t* dst = g_Aperm + (b * 32768 + kstep * 512 + lane * 4 + q);
#pragma unroll
        for (int slab = 0; slab < 4; ++slab) {
            float li = -3.0f + (float)(slab * 16 + rbase) * STEP;
            float d0 = li - xx.x;
            float d1 = li - xx.z;
            dst[slab * 128] = pack_bf16(ex2f(d0 * d0 * EX2C), ex2f(d1 * d1 * EX2C));
        }
    } else {
        // ---- Z part: one uint2 (4 bf16) per thread ----
        int flat = (bx - 512) * 256 + t;    // 0 .. 2,621,439
        int lane = flat & 31;
        int rem  = flat >> 5;               // nc + 5*(kstep + 64*(jt + 16*b))
        int nc   = rem % 5;
        int rest = rem / 5;
        int kstep = rest & 63;
        int jtb   = rest >> 6;
        int jt = jtb & 15, b = jtb >> 4;

        int klo = kstep * 16 + ((lane & 3) << 1);
        int n   = nc * 8 + (lane >> 2);
        int jl  = n / 10;
        int c   = n - jl * 10;
        float lj = -3.0f + (float)(jt * 4 + jl) * STEP;

        float4 xA = *(const float4*)(X + (size_t)(b * NN + klo) * 2);
        float4 xB = *(const float4*)(X + (size_t)(b * NN + klo + 8) * 2);
        float dA0 = lj - xA.y, dA1 = lj - xA.w;
        float dB0 = lj - xB.y, dB1 = lj - xB.w;
        float b0 = ex2f(dA0 * dA0 * EX2C);
        float b1 = ex2f(dA1 * dA1 * EX2C);
        float b8 = ex2f(dB0 * dB0 * EX2C);
        float b9 = ex2f(dB1 * dB1 * EX2C);

        float y0, y1, y8, y9;
        if (c == 0)      { y0 = y1 = y8 = y9 = 1.0f; }
        else if (c == 9) { y0 = y1 = y8 = y9 = 0.0f; }
        else {
            const float* yp = Y + (size_t)b * (NN * 8) + (size_t)klo * 8 + (c - 1);
            y0 = yp[0];  y1 = yp[8];
            y8 = yp[64]; y9 = yp[72];
        }
        uint2 z;
        z.x = pack_bf16(b0 * y0, b1 * y1);
        z.y = pack_bf16(b8 * y8, b9 * y9);
        g_Zperm[flat] = z;
    }
}

// ---------- main: grid 256 = b(16) x jt(16), 512 thr (2 K-groups) ----------
// Barrier-free streaming GEMM; smem only for the cross-group epilogue.
__global__ __launch_bounds__(512, 2)
void rkhs_mma_kernel(float* __restrict__ out)
{
    __shared__ __align__(16) float sD[2560];

    const int bx = blockIdx.x;
    const int jt = bx & 15;
    const int b  = bx >> 4;

    const int t    = threadIdx.x;
    const int ks   = t >> 8;            // K-group 0/1
    const int tl   = t & 255;
    const int lane = tl & 31;
    const int wid  = tl >> 5;
    const int slab = wid & 3;
    const int nh   = wid >> 2;
    const int nc0  = nh * 3;
    const int ncnt = nh ? 2 : 3;

    float acc[3][4];
#pragma unroll
    for (int a = 0; a < 3; ++a)
#pragma unroll
        for (int r = 0; r < 4; ++r) acc[a][r] = 0.0f;

    // A: uint4 idx = b*8192 + kstep*128 + slab*32 + lane, kstep = ks*32 + ch*4 + kst
    const uint4* gA = (const uint4*)g_Aperm + (size_t)b * 8192 + ks * 4096
                      + slab * 32 + lane;
    // Z: uint2 idx = (((b*16+jt)*64 + kstep)*5 + nc)*32 + lane
    const uint2* gZ = g_Zperm + (((size_t)(b * 16 + jt) * 64 + ks * 32) * 5) * 32
                      + (nc0 * 32) + lane;

#pragma unroll 2
    for (int ch = 0; ch < 8; ++ch) {
        uint4 af[4];
        uint2 zf[4][3];
#pragma unroll
        for (int kst = 0; kst < 4; ++kst)
            af[kst] = __ldg(gA + (ch * 4 + kst) * 128);
#pragma unroll
        for (int kst = 0; kst < 4; ++kst)
#pragma unroll
            for (int cc = 0; cc < 3; ++cc)
                if (cc < ncnt)
                    zf[kst][cc] = __ldg(gZ + ((ch * 4 + kst) * 5 + cc) * 32);
#pragma unroll
        for (int kst = 0; kst < 4; ++kst)
#pragma unroll
            for (int cc = 0; cc < 3; ++cc)
                if (cc < ncnt)
                    MMA_BF16(acc[cc], af[kst], zf[kst][cc]);
    }

    // ---- cross-group reduce + normalize + store ----
    __syncthreads();
    if (ks == 1) {
#pragma unroll
        for (int cc = 0; cc < 3; ++cc) {
            if (cc < ncnt) {
                float4 v = make_float4(acc[cc][0], acc[cc][1], acc[cc][2], acc[cc][3]);
                *(float4*)(sD + (((nc0 + cc) * 4 + slab) * 32 + lane) * 4) = v;
            }
        }
    }
    __syncthreads();
    if (ks == 0) {
#pragma unroll
        for (int cc = 0; cc < 3; ++cc) {
            if (cc < ncnt) {
                float4* p4 = (float4*)(sD + (((nc0 + cc) * 4 + slab) * 32 + lane) * 4);
                float4 v = *p4;
                v.x += acc[cc][0]; v.y += acc[cc][1];
                v.z += acc[cc][2]; v.w += acc[cc][3];
                *p4 = v;
            }
        }
    }
    __syncthreads();

#pragma unroll
    for (int rep = 0; rep < 5; ++rep) {
        int o = t + rep * 512;
        if (o < 2304) {
            int i   = o / 36;
            int rem = o - i * 36;
            int j   = rem / 9;
            int c   = rem - j * 9;
            int sl = i >> 4, rr = i & 15, half = rr >> 3, r8 = rr & 7;
            int col  = j * 10 + c;
            int idx  = (((col >> 3) * 4 + sl) * 32 + r8 * 4 + ((col & 7) >> 1)) * 4
                       + half * 2 + (col & 1);
            int colD = j * 10;
            int idxD = (((colD >> 3) * 4 + sl) * 32 + r8 * 4 + ((colD & 7) >> 1)) * 4
                       + half * 2 + (colD & 1);
            float dens = sD[idxD];
            float v = (c == 0) ? dens : sD[idx] / (dens + 1e-6f);
            out[8192 + (size_t)(b * 4096 + i * 64 + jt * 4 + j) * 9 + c] = v;
        }
    }
}

extern "C" void kernel_launch(void* const* d_in, const int* in_sizes, int n_in,
                              void* d_out, int out_size)
{
    const float* X = (const float*)d_in[0];
    const float* Y = (const float*)d_in[1];
    float* out = (float*)d_out;

    rkhs_prep_kernel<<<10752, 256>>>(X, Y, out);
    rkhs_mma_kernel<<<256, 512>>>(out);
}

// round 12
// speedup vs baseline: 1.2162x; 1.2162x over previous
#include <cuda_runtime.h>
#include <cstdint>

// out[b,i,j,c] = sum_k exp(-2(li-x0k)^2)*exp(-2(lj-x1k)^2)*Yb[k,c]
// GEMM: C[64 x 640] = A[64 x 1024] * Z[1024 x 640], bf16 mma m16n8k16.
// Z-slice per (b,jt) is built in SMEM (80KB) by the consuming CTA itself.
#define NB    16
#define NN    1024
#define STEP  (6.0f / 63.0f)
#define EX2C  (-2.885390081777927f)   // -2*log2(e)

// A frags: u32 idx = b*32768 + kstep*512 + slab*128 + lane*4 + q
__device__ __align__(16) uint32_t g_Aperm[NB * 64 * 4 * 32 * 4];

__device__ __forceinline__ float ex2f(float x) {
    float r; asm("ex2.approx.ftz.f32 %0, %1;" : "=f"(r) : "f"(x)); return r;
}
__device__ __forceinline__ uint32_t pack_bf16(float lo, float hi) {
    uint32_t d;
    asm("cvt.rn.bf16x2.f32 %0, %1, %2;" : "=r"(d) : "f"(hi), "f"(lo));
    return d;
}
#define MMA_BF16(d, a, bb) \
    asm volatile("mma.sync.aligned.m16n8k16.row.col.f32.bf16.bf16.f32 " \
        "{%0,%1,%2,%3}, {%4,%5,%6,%7}, {%8,%9}, {%0,%1,%2,%3};" \
        : "+f"(d[0]), "+f"(d[1]), "+f"(d[2]), "+f"(d[3]) \
        : "r"(a.x), "r"(a.y), "r"(a.z), "r"(a.w), "r"(bb.x), "r"(bb.y))

// ---------- prep: A frags only + grid coords (512 CTAs) ----------
__global__ __launch_bounds__(256)
void rkhs_prep_kernel(const float* __restrict__ X, float* __restrict__ out)
{
    int tid = blockIdx.x * blockDim.x + threadIdx.x;
    if (tid < 4096) {
        out[tid * 2 + 0] = -3.0f + (float)(tid >> 6) * STEP;
        out[tid * 2 + 1] = -3.0f + (float)(tid & 63) * STEP;
    }
    int q     = tid & 3;
    int lane  = (tid >> 2) & 31;
    int kstep = (tid >> 7) & 63;
    int b     = tid >> 13;

    int kb = kstep * 16 + ((lane & 3) << 1) + ((q >> 1) << 3);
    float4 xx = *(const float4*)(X + (size_t)(b * NN + kb) * 2);
    int rbase = (lane >> 2) + ((q & 1) << 3);
    uint32_t* dst = g_Aperm + (b * 32768 + kstep * 512 + lane * 4 + q);
#pragma unroll
    for (int slab = 0; slab < 4; ++slab) {
        float li = -3.0f + (float)(slab * 16 + rbase) * STEP;
        float d0 = li - xx.x;
        float d1 = li - xx.z;
        dst[slab * 128] = pack_bf16(ex2f(d0 * d0 * EX2C), ex2f(d1 * d1 * EX2C));
    }
}

// ---------- main: grid 256 = (b,jt), 512 thr = 2 K-groups ----------
// Phase 1: build this CTA's Z slice [64 kstep][5 nc][32 lane] uint2 in smem.
// Phase 2: barrier-free mma mainloop (A from gmem, Z from smem).
#define ZSLOTS (64 * 5 * 32)      // 10240 uint2 = 81920 B

__global__ __launch_bounds__(512, 2)
void rkhs_mma_kernel(const float* __restrict__ X, const float* __restrict__ Y,
                     float* __restrict__ out)
{
    extern __shared__ __align__(16) uint2 sZ[];   // ZSLOTS

    const int bx = blockIdx.x;
    const int jt = bx & 15;
    const int b  = bx >> 4;
    const int t  = threadIdx.x;

    // ===== Phase 1: Z build =====
    {
        const float ljbase = -3.0f + (float)(jt * 4) * STEP;
        const float* yb = Y + (size_t)b * (NN * 8);
#pragma unroll
        for (int gg = 0; gg < 4; ++gg) {
            int g = gg * 512 + t;              // 0..2047 = kstep*32 + lane
            int kstep = g >> 5;
            int ln    = g & 31;
            int klo = kstep * 16 + ((ln & 3) << 1);
            int r   = ln >> 2;
            float4 xA = *(const float4*)(X + (size_t)(b * NN + klo) * 2);
            float4 xB = *(const float4*)(X + (size_t)(b * NN + klo + 8) * 2);
#pragma unroll
            for (int nc = 0; nc < 5; ++nc) {
                int n  = nc * 8 + r;
                int jl = n / 10;
                int c  = n - jl * 10;
                float lj = ljbase + (float)jl * STEP;
                float d0 = lj - xA.y, d1 = lj - xA.w;
                float d8 = lj - xB.y, d9 = lj - xB.w;
                float e0 = ex2f(d0 * d0 * EX2C);
                float e1 = ex2f(d1 * d1 * EX2C);
                float e8 = ex2f(d8 * d8 * EX2C);
                float e9 = ex2f(d9 * d9 * EX2C);
                uint2 z;
                if (c == 0) {
                    z.x = pack_bf16(e0, e1);
                    z.y = pack_bf16(e8, e9);
                } else if (c == 9) {
                    z.x = 0u; z.y = 0u;
                } else {
                    const float* yp = yb + (size_t)klo * 8 + (c - 1);
                    z.x = pack_bf16(e0 * yp[0],  e1 * yp[8]);
                    z.y = pack_bf16(e8 * yp[64], e9 * yp[72]);
                }
                sZ[(kstep * 5 + nc) * 32 + ln] = z;
            }
        }
    }
    __syncthreads();

    // ===== Phase 2: mma mainloop =====
    const int ks   = t >> 8;
    const int tl   = t & 255;
    const int lane = tl & 31;
    const int wid  = tl >> 5;
    const int slab = wid & 3;
    const int nh   = wid >> 2;
    const int nc0  = nh * 3;
    const int ncnt = nh ? 2 : 3;

    float acc[3][4];
#pragma unroll
    for (int a = 0; a < 3; ++a)
#pragma unroll
        for (int r = 0; r < 4; ++r) acc[a][r] = 0.0f;

    const uint4* gA = (const uint4*)g_Aperm + (size_t)b * 8192 + ks * 4096
                      + slab * 32 + lane;
    const uint2* zb = sZ + (size_t)(ks * 32 * 5 + nc0) * 32 + lane;

#pragma unroll 2
    for (int ch = 0; ch < 8; ++ch) {
        uint4 af[4];
        uint2 zf[4][3];
#pragma unroll
        for (int kst = 0; kst < 4; ++kst)
            af[kst] = __ldg(gA + (ch * 4 + kst) * 128);
#pragma unroll
        for (int kst = 0; kst < 4; ++kst)
#pragma unroll
            for (int cc = 0; cc < 3; ++cc)
                if (cc < ncnt)
                    zf[kst][cc] = zb[((ch * 4 + kst) * 5 + cc) * 32];
#pragma unroll
        for (int kst = 0; kst < 4; ++kst)
#pragma unroll
            for (int cc = 0; cc < 3; ++cc)
                if (cc < ncnt)
                    MMA_BF16(acc[cc], af[kst], zf[kst][cc]);
    }

    // ===== epilogue: cross-group reduce + normalize + store =====
    __syncthreads();                 // all Z reads done; alias sZ as sD
    float* sD = (float*)sZ;

    if (ks == 1) {
#pragma unroll
        for (int cc = 0; cc < 3; ++cc) {
            if (cc < ncnt) {
                float4 v = make_float4(acc[cc][0], acc[cc][1], acc[cc][2], acc[cc][3]);
                *(float4*)(sD + (((nc0 + cc) * 4 + slab) * 32 + lane) * 4) = v;
            }
        }
    }
    __syncthreads();
    if (ks == 0) {
#pragma unroll
        for (int cc = 0; cc < 3; ++cc) {
            if (cc < ncnt) {
                float4* p4 = (float4*)(sD + (((nc0 + cc) * 4 + slab) * 32 + lane) * 4);
                float4 v = *p4;
                v.x += acc[cc][0]; v.y += acc[cc][1];
                v.z += acc[cc][2]; v.w += acc[cc][3];
                *p4 = v;
            }
        }
    }
    __syncthreads();

#pragma unroll
    for (int rep = 0; rep < 5; ++rep) {
        int o = t + rep * 512;
        if (o < 2304) {
            int i   = o / 36;
            int rem = o - i * 36;
            int j   = rem / 9;
            int c   = rem - j * 9;
            int sl = i >> 4, rr = i & 15, half = rr >> 3, r8 = rr & 7;
            int col  = j * 10 + c;
            int idx  = (((col >> 3) * 4 + sl) * 32 + r8 * 4 + ((col & 7) >> 1)) * 4
                       + half * 2 + (col & 1);
            int colD = j * 10;
            int idxD = (((colD >> 3) * 4 + sl) * 32 + r8 * 4 + ((colD & 7) >> 1)) * 4
                       + half * 2 + (colD & 1);
            float dens = sD[idxD];
            float v = (c == 0) ? dens : sD[idx] / (dens + 1e-6f);
            out[8192 + (size_t)(b * 4096 + i * 64 + jt * 4 + j) * 9 + c] = v;
        }
    }
}

extern "C" void kernel_launch(void* const* d_in, const int* in_sizes, int n_in,
                              void* d_out, int out_size)
{
    const float* X = (const float*)d_in[0];
    const float* Y = (const float*)d_in[1];
    float* out = (float*)d_out;

    const int zbytes = ZSLOTS * (int)sizeof(uint2);   // 81920
    cudaFuncSetAttribute(rkhs_mma_kernel,
                         cudaFuncAttributeMaxDynamicSharedMemorySize, zbytes);

    rkhs_prep_kernel<<<512, 256>>>(X, out);
    rkhs_mma_kernel<<<256, 512, zbytes>>>(X, Y, out);
}

// round 13
// speedup vs baseline: 1.3458x; 1.1065x over previous
#include <cuda_runtime.h>
#include <cstdint>

// out[b,i,j,c] = sum_k exp(-2(li-x0k)^2)*exp(-2(lj-x1k)^2)*Yb[k,c]
// GEMM: C[64 x 640] = A[64 x 1024] * Z[1024 x 640], bf16 mma m16n8k16.
// Z-slice per (b,jt) built in SMEM; build is per-(kstep,q,jl) item so each
// B-exp is computed once and reused across all 10 channels.
#define NB    16
#define NN    1024
#define STEP  (6.0f / 63.0f)
#define EX2C  (-2.885390081777927f)   // -2*log2(e)

// A frags: u32 idx = b*32768 + kstep*512 + slab*128 + lane*4 + q
__device__ __align__(16) uint32_t g_Aperm[NB * 64 * 4 * 32 * 4];

__device__ __forceinline__ float ex2f(float x) {
    float r; asm("ex2.approx.ftz.f32 %0, %1;" : "=f"(r) : "f"(x)); return r;
}
__device__ __forceinline__ uint32_t pack_bf16(float lo, float hi) {
    uint32_t d;
    asm("cvt.rn.bf16x2.f32 %0, %1, %2;" : "=r"(d) : "f"(hi), "f"(lo));
    return d;
}
#define MMA_BF16(d, a, bb) \
    asm volatile("mma.sync.aligned.m16n8k16.row.col.f32.bf16.bf16.f32 " \
        "{%0,%1,%2,%3}, {%4,%5,%6,%7}, {%8,%9}, {%0,%1,%2,%3};" \
        : "+f"(d[0]), "+f"(d[1]), "+f"(d[2]), "+f"(d[3]) \
        : "r"(a.x), "r"(a.y), "r"(a.z), "r"(a.w), "r"(bb.x), "r"(bb.y))

// ---------- prep: A frags + grid coords (512 CTAs) ----------
__global__ __launch_bounds__(256)
void rkhs_prep_kernel(const float* __restrict__ X, float* __restrict__ out)
{
    int tid = blockIdx.x * blockDim.x + threadIdx.x;
    if (tid < 4096) {
        out[tid * 2 + 0] = -3.0f + (float)(tid >> 6) * STEP;
        out[tid * 2 + 1] = -3.0f + (float)(tid & 63) * STEP;
    }
    int q     = tid & 3;
    int lane  = (tid >> 2) & 31;
    int kstep = (tid >> 7) & 63;
    int b     = tid >> 13;

    int kb = kstep * 16 + ((lane & 3) << 1) + ((q >> 1) << 3);
    float4 xx = *(const float4*)(X + (size_t)(b * NN + kb) * 2);
    int rbase = (lane >> 2) + ((q & 1) << 3);
    uint32_t* dst = g_Aperm + (b * 32768 + kstep * 512 + lane * 4 + q);
#pragma unroll
    for (int slab = 0; slab < 4; ++slab) {
        float li = -3.0f + (float)(slab * 16 + rbase) * STEP;
        float d0 = li - xx.x;
        float d1 = li - xx.z;
        dst[slab * 128] = pack_bf16(ex2f(d0 * d0 * EX2C), ex2f(d1 * d1 * EX2C));
    }
}

// ---------- main: grid 256 = (b,jt), 512 thr = 2 K-groups ----------
#define ZSLOTS (64 * 5 * 32)      // 10240 uint2 = 81920 B

__global__ __launch_bounds__(512, 2)
void rkhs_mma_kernel(const float* __restrict__ X, const float* __restrict__ Y,
                     float* __restrict__ out)
{
    extern __shared__ __align__(16) uint2 sZ[];   // [kstep*5+nc][32]

    const int bx = blockIdx.x;
    const int jt = bx & 15;
    const int b  = bx >> 4;
    const int t  = threadIdx.x;

    // ===== Phase 1: Z build, item = (kstep, q, jl); 2 items/thread =====
    {
        const float* yb = Y + (size_t)b * (NN * 8);
#pragma unroll
        for (int item = 0; item < 2; ++item) {
            int w     = item * 512 + t;        // 0..1023
            int jl    = w & 3;
            int q     = (w >> 2) & 3;
            int kstep = w >> 4;
            int klo   = kstep * 16 + q * 2;    // k's: klo, klo+1, klo+8, klo+9
            float lj  = -3.0f + (float)(jt * 4 + jl) * STEP;

            float4 xA = *(const float4*)(X + (size_t)(b * NN + klo) * 2);
            float4 xB = *(const float4*)(X + (size_t)(b * NN + klo + 8) * 2);
            float dA0 = lj - xA.y, dA1 = lj - xA.w;
            float dB0 = lj - xB.y, dB1 = lj - xB.w;
            float e0 = ex2f(dA0 * dA0 * EX2C);
            float e1 = ex2f(dA1 * dA1 * EX2C);
            float e8 = ex2f(dB0 * dB0 * EX2C);
            float e9 = ex2f(dB1 * dB1 * EX2C);

            // Y rows for the 4 k's (8 channels each), vectorized
            const float4* y0p = (const float4*)(yb + (size_t)klo * 8);
            float4 y0a = y0p[0],  y0b = y0p[1];    // k = klo
            float4 y1a = y0p[2],  y1b = y0p[3];    // k = klo+1
            float4 y8a = y0p[16], y8b = y0p[17];   // k = klo+8
            float4 y9a = y0p[18], y9b = y0p[19];   // k = klo+9

            float Y0[8] = {y0a.x, y0a.y, y0a.z, y0a.w, y0b.x, y0b.y, y0b.z, y0b.w};
            float Y1[8] = {y1a.x, y1a.y, y1a.z, y1a.w, y1b.x, y1b.y, y1b.z, y1b.w};
            float Y8[8] = {y8a.x, y8a.y, y8a.z, y8a.w, y8b.x, y8b.y, y8b.z, y8b.w};
            float Y9[8] = {y9a.x, y9a.y, y9a.z, y9a.w, y9b.x, y9b.y, y9b.z, y9b.w};

            uint2* zk = sZ + (size_t)kstep * 5 * 32 + q;   // + nc*32 + r*4
            int nbase = jl * 10;                            // n = nbase + c
#pragma unroll
            for (int c = 0; c < 10; ++c) {
                int n  = nbase + c;
                int nc = n >> 3;
                int r  = n & 7;
                uint2 z;
                if (c == 0) {
                    z.x = pack_bf16(e0, e1);
                    z.y = pack_bf16(e8, e9);
                } else if (c == 9) {
                    z.x = 0u; z.y = 0u;
                } else {
                    z.x = pack_bf16(e0 * Y0[c - 1], e1 * Y1[c - 1]);
                    z.y = pack_bf16(e8 * Y8[c - 1], e9 * Y9[c - 1]);
                }
                zk[nc * 32 + r * 4] = z;
            }
        }
    }
    __syncthreads();

    // ===== Phase 2: barrier-free mma mainloop =====
    const int ks   = t >> 8;
    const int tl   = t & 255;
    const int lane = tl & 31;
    const int wid  = tl >> 5;
    const int slab = wid & 3;
    const int nh   = wid >> 2;
    const int nc0  = nh * 3;
    const int ncnt = nh ? 2 : 3;

    float acc[3][4];
#pragma unroll
    for (int a = 0; a < 3; ++a)
#pragma unroll
        for (int r = 0; r < 4; ++r) acc[a][r] = 0.0f;

    const uint4* gA = (const uint4*)g_Aperm + (size_t)b * 8192 + ks * 4096
                      + slab * 32 + lane;
    const uint2* zb = sZ + (size_t)(ks * 32 * 5 + nc0) * 32 + lane;

#pragma unroll 2
    for (int ch = 0; ch < 8; ++ch) {
        uint4 af[4];
        uint2 zf[4][3];
#pragma unroll
        for (int kst = 0; kst < 4; ++kst)
            af[kst] = __ldg(gA + (ch * 4 + kst) * 128);
#pragma unroll
        for (int kst = 0; kst < 4; ++kst)
#pragma unroll
            for (int cc = 0; cc < 3; ++cc)
                if (cc < ncnt)
                    zf[kst][cc] = zb[((ch * 4 + kst) * 5 + cc) * 32];
#pragma unroll
        for (int kst = 0; kst < 4; ++kst)
#pragma unroll
            for (int cc = 0; cc < 3; ++cc)
                if (cc < ncnt)
                    MMA_BF16(acc[cc], af[kst], zf[kst][cc]);
    }

    // ===== epilogue: cross-group reduce + normalize + store =====
    __syncthreads();
    float* sD = (float*)sZ;

    if (ks == 1) {
#pragma unroll
        for (int cc = 0; cc < 3; ++cc) {
            if (cc < ncnt) {
                float4 v = make_float4(acc[cc][0], acc[cc][1], acc[cc][2], acc[cc][3]);
                *(float4*)(sD + (((nc0 + cc) * 4 + slab) * 32 + lane) * 4) = v;
            }
        }
    }
    __syncthreads();
    if (ks == 0) {
#pragma unroll
        for (int cc = 0; cc < 3; ++cc) {
            if (cc < ncnt) {
                float4* p4 = (float4*)(sD + (((nc0 + cc) * 4 + slab) * 32 + lane) * 4);
                float4 v = *p4;
                v.x += acc[cc][0]; v.y += acc[cc][1];
                v.z += acc[cc][2]; v.w += acc[cc][3];
                *p4 = v;
            }
        }
    }
    __syncthreads();

#pragma unroll
    for (int rep = 0; rep < 5; ++rep) {
        int o = t + rep * 512;
        if (o < 2304) {
            int i   = o / 36;
            int rem = o - i * 36;
            int j   = rem / 9;
            int c   = rem - j * 9;
            int sl = i >> 4, rr = i & 15, half = rr >> 3, r8 = rr & 7;
            int col  = j * 10 + c;
            int idx  = (((col >> 3) * 4 + sl) * 32 + r8 * 4 + ((col & 7) >> 1)) * 4
                       + half * 2 + (col & 1);
            int colD = j * 10;
            int idxD = (((colD >> 3) * 4 + sl) * 32 + r8 * 4 + ((colD & 7) >> 1)) * 4
                       + half * 2 + (colD & 1);
            float dens = sD[idxD];
            float v = (c == 0) ? dens : sD[idx] / (dens + 1e-6f);
            out[8192 + (size_t)(b * 4096 + i * 64 + jt * 4 + j) * 9 + c] = v;
        }
    }
}

extern "C" void kernel_launch(void* const* d_in, const int* in_sizes, int n_in,
                              void* d_out, int out_size)
{
    const float* X = (const float*)d_in[0];
    const float* Y = (const float*)d_in[1];
    float* out = (float*)d_out;

    const int zbytes = ZSLOTS * (int)sizeof(uint2);   // 81920
    cudaFuncSetAttribute(rkhs_mma_kernel,
                         cudaFuncAttributeMaxDynamicSharedMemorySize, zbytes);

    rkhs_prep_kernel<<<512, 256>>>(X, out);
    rkhs_mma_kernel<<<256, 512, zbytes>>>(X, Y, out);
}

// round 14
// speedup vs baseline: 1.3662x; 1.0152x over previous
#include <cuda_runtime.h>
#include <cstdint>

// out[b,i,j,c] = sum_k exp(-2(li-x0k)^2)*exp(-2(lj-x1k)^2)*Yb[k,c]
// GEMM: C[64 x 640] = A[64 x 1024] * Z[1024 x 640], bf16 mma m16n8k16.
// Each K-group (256 thr) builds its own Z half in smem and syncs with a
// group-scoped named barrier -> the two halves pipeline independently.
#define NB    16
#define NN    1024
#define STEP  (6.0f / 63.0f)
#define EX2C  (-2.885390081777927f)   // -2*log2(e)

// A frags: u32 idx = b*32768 + kstep*512 + slab*128 + lane*4 + q
__device__ __align__(16) uint32_t g_Aperm[NB * 64 * 4 * 32 * 4];

__device__ __forceinline__ float ex2f(float x) {
    float r; asm("ex2.approx.ftz.f32 %0, %1;" : "=f"(r) : "f"(x)); return r;
}
__device__ __forceinline__ uint32_t pack_bf16(float lo, float hi) {
    uint32_t d;
    asm("cvt.rn.bf16x2.f32 %0, %1, %2;" : "=r"(d) : "f"(hi), "f"(lo));
    return d;
}
#define MMA_BF16(d, a, bb) \
    asm volatile("mma.sync.aligned.m16n8k16.row.col.f32.bf16.bf16.f32 " \
        "{%0,%1,%2,%3}, {%4,%5,%6,%7}, {%8,%9}, {%0,%1,%2,%3};" \
        : "+f"(d[0]), "+f"(d[1]), "+f"(d[2]), "+f"(d[3]) \
        : "r"(a.x), "r"(a.y), "r"(a.z), "r"(a.w), "r"(bb.x), "r"(bb.y))
#define GROUP_BAR(id) \
    asm volatile("bar.sync %0, 256;" :: "r"(id) : "memory")

// ---------- prep: A frags + grid coords (512 CTAs) ----------
__global__ __launch_bounds__(256)
void rkhs_prep_kernel(const float* __restrict__ X, float* __restrict__ out)
{
    int tid = blockIdx.x * blockDim.x + threadIdx.x;
    if (tid < 4096) {
        out[tid * 2 + 0] = -3.0f + (float)(tid >> 6) * STEP;
        out[tid * 2 + 1] = -3.0f + (float)(tid & 63) * STEP;
    }
    int q     = tid & 3;
    int lane  = (tid >> 2) & 31;
    int kstep = (tid >> 7) & 63;
    int b     = tid >> 13;

    int kb = kstep * 16 + ((lane & 3) << 1) + ((q >> 1) << 3);
    float4 xx = *(const float4*)(X + (size_t)(b * NN + kb) * 2);
    int rbase = (lane >> 2) + ((q & 1) << 3);
    uint32_t* dst = g_Aperm + (b * 32768 + kstep * 512 + lane * 4 + q);
#pragma unroll
    for (int slab = 0; slab < 4; ++slab) {
        float li = -3.0f + (float)(slab * 16 + rbase) * STEP;
        float d0 = li - xx.x;
        float d1 = li - xx.z;
        dst[slab * 128] = pack_bf16(ex2f(d0 * d0 * EX2C), ex2f(d1 * d1 * EX2C));
    }
}

// ---------- main: grid 256 = (b,jt), 512 thr = 2 independent K-groups ----------
#define ZSLOTS (64 * 5 * 32)      // 10240 uint2 = 81920 B

__global__ __launch_bounds__(512, 2)
void rkhs_mma_kernel(const float* __restrict__ X, const float* __restrict__ Y,
                     float* __restrict__ out)
{
    extern __shared__ __align__(16) uint2 sZ[];   // [kstep*5+nc][32]

    const int bx = blockIdx.x;
    const int jt = bx & 15;
    const int b  = bx >> 4;
    const int t  = threadIdx.x;

    const int ks = t >> 8;            // K-group 0/1
    const int tl = t & 255;

    // ===== Phase 1: build THIS group's Z half (512 items, 2/thread) =====
    {
        const float* yb = Y + (size_t)b * (NN * 8);
#pragma unroll
        for (int item = 0; item < 2; ++item) {
            int w     = item * 256 + tl;        // 0..511
            int jl    = w & 3;
            int q     = (w >> 2) & 3;
            int kstep = ks * 32 + (w >> 4);     // group-local half
            int klo   = kstep * 16 + q * 2;     // k's: klo, klo+1, klo+8, klo+9
            float lj  = -3.0f + (float)(jt * 4 + jl) * STEP;

            float4 xA = *(const float4*)(X + (size_t)(b * NN + klo) * 2);
            float4 xB = *(const float4*)(X + (size_t)(b * NN + klo + 8) * 2);
            float dA0 = lj - xA.y, dA1 = lj - xA.w;
            float dB0 = lj - xB.y, dB1 = lj - xB.w;
            float e0 = ex2f(dA0 * dA0 * EX2C);
            float e1 = ex2f(dA1 * dA1 * EX2C);
            float e8 = ex2f(dB0 * dB0 * EX2C);
            float e9 = ex2f(dB1 * dB1 * EX2C);

            const float4* y0p = (const float4*)(yb + (size_t)klo * 8);
            float4 y0a = y0p[0],  y0b = y0p[1];
            float4 y1a = y0p[2],  y1b = y0p[3];
            float4 y8a = y0p[16], y8b = y0p[17];
            float4 y9a = y0p[18], y9b = y0p[19];

            float Y0[8] = {y0a.x, y0a.y, y0a.z, y0a.w, y0b.x, y0b.y, y0b.z, y0b.w};
            float Y1[8] = {y1a.x, y1a.y, y1a.z, y1a.w, y1b.x, y1b.y, y1b.z, y1b.w};
            float Y8[8] = {y8a.x, y8a.y, y8a.z, y8a.w, y8b.x, y8b.y, y8b.z, y8b.w};
            float Y9[8] = {y9a.x, y9a.y, y9a.z, y9a.w, y9b.x, y9b.y, y9b.z, y9b.w};

            uint2* zk = sZ + (size_t)kstep * 5 * 32 + q;
            int nbase = jl * 10;
#pragma unroll
            for (int c = 0; c < 10; ++c) {
                int n  = nbase + c;
                int nc = n >> 3;
                int r  = n & 7;
                uint2 z;
                if (c == 0) {
                    z.x = pack_bf16(e0, e1);
                    z.y = pack_bf16(e8, e9);
                } else if (c == 9) {
                    z.x = 0u; z.y = 0u;
                } else {
                    z.x = pack_bf16(e0 * Y0[c - 1], e1 * Y1[c - 1]);
                    z.y = pack_bf16(e8 * Y8[c - 1], e9 * Y9[c - 1]);
                }
                zk[nc * 32 + r * 4] = z;
            }
        }
    }
    GROUP_BAR(1 + ks);                // group-scoped: our half is ready

    // ===== Phase 2: barrier-free mma mainloop (own half only) =====
    const int lane = tl & 31;
    const int wid  = tl >> 5;
    const int slab = wid & 3;
    const int nh   = wid >> 2;
    const int nc0  = nh * 3;
    const int ncnt = nh ? 2 : 3;

    float acc[3][4];
#pragma unroll
    for (int a = 0; a < 3; ++a)
#pragma unroll
        for (int r = 0; r < 4; ++r) acc[a][r] = 0.0f;

    const uint4* gA = (const uint4*)g_Aperm + (size_t)b * 8192 + ks * 4096
                      + slab * 32 + lane;
    const uint2* zb = sZ + (size_t)(ks * 32 * 5 + nc0) * 32 + lane;

#pragma unroll 2
    for (int ch = 0; ch < 8; ++ch) {
        uint4 af[4];
        uint2 zf[4][3];
#pragma unroll
        for (int kst = 0; kst < 4; ++kst)
            af[kst] = __ldg(gA + (ch * 4 + kst) * 128);
#pragma unroll
        for (int kst = 0; kst < 4; ++kst)
#pragma unroll
            for (int cc = 0; cc < 3; ++cc)
                if (cc < ncnt)
                    zf[kst][cc] = zb[((ch * 4 + kst) * 5 + cc) * 32];
#pragma unroll
        for (int kst = 0; kst < 4; ++kst)
#pragma unroll
            for (int cc = 0; cc < 3; ++cc)
                if (cc < ncnt)
                    MMA_BF16(acc[cc], af[kst], zf[kst][cc]);
    }

    // ===== epilogue: cross-group reduce + normalize + store =====
    __syncthreads();                  // both groups done; alias sZ as sD
    float* sD = (float*)sZ;

    if (ks == 1) {
#pragma unroll
        for (int cc = 0; cc < 3; ++cc) {
            if (cc < ncnt) {
                float4 v = make_float4(acc[cc][0], acc[cc][1], acc[cc][2], acc[cc][3]);
                *(float4*)(sD + (((nc0 + cc) * 4 + slab) * 32 + lane) * 4) = v;
            }
        }
    }
    __syncthreads();
    if (ks == 0) {
#pragma unroll
        for (int cc = 0; cc < 3; ++cc) {
            if (cc < ncnt) {
                float4* p4 = (float4*)(sD + (((nc0 + cc) * 4 + slab) * 32 + lane) * 4);
                float4 v = *p4;
                v.x += acc[cc][0]; v.y += acc[cc][1];
                v.z += acc[cc][2]; v.w += acc[cc][3];
                *p4 = v;
            }
        }
    }
    __syncthreads();

#pragma unroll
    for (int rep = 0; rep < 5; ++rep) {
        int o = t + rep * 512;
        if (o < 2304) {
            int i   = o / 36;
            int rem = o - i * 36;
            int j   = rem / 9;
            int c   = rem - j * 9;
            int sl = i >> 4, rr = i & 15, half = rr >> 3, r8 = rr & 7;
            int col  = j * 10 + c;
            int idx  = (((col >> 3) * 4 + sl) * 32 + r8 * 4 + ((col & 7) >> 1)) * 4
                       + half * 2 + (col & 1);
            int colD = j * 10;
            int idxD = (((colD >> 3) * 4 + sl) * 32 + r8 * 4 + ((colD & 7) >> 1)) * 4
                       + half * 2 + (colD & 1);
            float dens = sD[idxD];
            float v = (c == 0) ? dens : sD[idx] / (dens + 1e-6f);
            out[8192 + (size_t)(b * 4096 + i * 64 + jt * 4 + j) * 9 + c] = v;
        }
    }
}

extern "C" void kernel_launch(void* const* d_in, const int* in_sizes, int n_in,
                              void* d_out, int out_size)
{
    const float* X = (const float*)d_in[0];
    const float* Y = (const float*)d_in[1];
    float* out = (float*)d_out;

    const int zbytes = ZSLOTS * (int)sizeof(uint2);   // 81920
    cudaFuncSetAttribute(rkhs_mma_kernel,
                         cudaFuncAttributeMaxDynamicSharedMemorySize, zbytes);

    rkhs_prep_kernel<<<512, 256>>>(X, out);
    rkhs_mma_kernel<<<256, 512, zbytes>>>(X, Y, out);
}